// round 8
// baseline (speedup 1.0000x reference)
#include <cuda_runtime.h>
#include <cstdint>

// Problem constants
constexpr int Hd = 1024;   // hidden
constexpr int Ff = 4096;   // intermediate
constexpr int NE = 8;      // experts
constexpr int NT = 2048;   // tokens
constexpr int NA = 2 * NT; // assignments (top-2)

// ---------------- device scratch (no allocations allowed) ----------------
__device__ int   g_cnt[NE];
__device__ int   g_tok[NE][NT];
__device__ float g_wt[NE][NT];
__device__ int   g_slot[NE][NT];
__device__ float g_h[(size_t)NA * Ff];   // 64 MB fp32 intermediate, row = tok*2+slot
__device__ float g_sbuf[2 * NT * Hd];    // per-rank-slot output buffers

// ---------------- helpers ----------------
__device__ __forceinline__ float f2tf(float x) {
    unsigned u;
    asm("cvt.rna.tf32.f32 %0, %1;" : "=r"(u) : "f"(x));
    return __uint_as_float(u);
}
__device__ __forceinline__ void mma8(float c[4], const unsigned a[4], const unsigned b[2]) {
    asm volatile(
        "mma.sync.aligned.m16n8k8.row.col.f32.tf32.tf32.f32 "
        "{%0,%1,%2,%3},{%4,%5,%6,%7},{%8,%9},{%0,%1,%2,%3};"
        : "+f"(c[0]), "+f"(c[1]), "+f"(c[2]), "+f"(c[3])
        : "r"(a[0]), "r"(a[1]), "r"(a[2]), "r"(a[3]), "r"(b[0]), "r"(b[1]));
}

// ---------------- small kernels ----------------
__global__ void zero_kernel() {
    if (threadIdx.x < NE) g_cnt[threadIdx.x] = 0;
}

// One warp per token: logits -> softmax -> top-2 -> softmax of the two PROBS.
__global__ void router_kernel(const float* __restrict__ x, const float* __restrict__ gw) {
    int tok  = blockIdx.x * 8 + (threadIdx.x >> 5);
    int lane = threadIdx.x & 31;
    if (tok >= NT) return;
    const float* xr = x + (size_t)tok * Hd;

    float acc[NE];
#pragma unroll
    for (int e = 0; e < NE; e++) acc[e] = 0.f;
    for (int i = lane; i < Hd; i += 32) {
        float xv = xr[i];
        const float* g = gw + i * NE;
#pragma unroll
        for (int e = 0; e < NE; e++) acc[e] = fmaf(xv, g[e], acc[e]);
    }
#pragma unroll
    for (int e = 0; e < NE; e++) {
#pragma unroll
        for (int o = 16; o > 0; o >>= 1) acc[e] += __shfl_xor_sync(0xffffffffu, acc[e], o);
    }
    if (lane == 0) {
        float m = acc[0];
#pragma unroll
        for (int e = 1; e < NE; e++) m = fmaxf(m, acc[e]);
        float p[NE], s = 0.f;
#pragma unroll
        for (int e = 0; e < NE; e++) { p[e] = expf(acc[e] - m); s += p[e]; }
        float inv = 1.f / s;
#pragma unroll
        for (int e = 0; e < NE; e++) p[e] *= inv;

        int i0 = 0;
#pragma unroll
        for (int e = 1; e < NE; e++) if (p[e] > p[i0]) i0 = e;
        int i1 = (i0 == 0) ? 1 : 0;
#pragma unroll
        for (int e = 0; e < NE; e++) if (e != i0 && p[e] > p[i1]) i1 = e;

        float eb = expf(p[i1] - p[i0]);       // <= 1
        float w0 = 1.f / (1.f + eb);
        float w1 = 1.f - w0;

        int s0 = atomicAdd(&g_cnt[i0], 1);
        g_tok[i0][s0] = tok; g_wt[i0][s0] = w0; g_slot[i0][s0] = 0;
        int s1 = atomicAdd(&g_cnt[i1], 1);
        g_tok[i1][s1] = tok; g_wt[i1][s1] = w1; g_slot[i1][s1] = 1;
    }
}

// ============================================================================
// Layout notes (both GEMMs), TK = 16:
//  A smem: [128 rows][16 words], k stored at word 4*((k%4) ^ ((row>>1)&3)) + k/4.
//    - staging: 4 conflict-free STS.32 per LDG.128 (XOR spreads rows over banks)
//    - fragment: one LDS.128 at word 4*(qc ^ perm(row)) gives k = qc+{0,4,8,12},
//      i.e. BOTH k8 steps; conflict-free (rows split 0/16 bank halves).
//  B smem: [16 k-rows][pitch words], pitch = 136 (128-wide tile) or 72 (64-wide):
//    - staging: contiguous STS.128 (128B per quarter-warp), conflict-free
//    - fragment: scalar LDS.32, bank = (8k + n) mod 32 -> 32 distinct banks
//      for k = qc(+4) in a k8 step and n = n0 + qr (n0 multiple of 8).
// ============================================================================

// ============================================================================
// GEMM1: block 128(M) x 64(N), 256 thr, warps 2x4 (tile 64x16 per matrix),
// fused: h[aid] = silu(X Wg) * (X Wu)
// ============================================================================
__global__ void __launch_bounds__(256) gemm1_kernel(
    const float* __restrict__ x,
    const float* __restrict__ w_gate,
    const float* __restrict__ w_up)
{
    int e = blockIdx.z;
    int cnt = g_cnt[e];
    int row0 = blockIdx.y * 128;
    if (row0 >= cnt) return;
    int col0 = blockIdx.x * 64;
    const float* Bg = w_gate + (size_t)e * Hd * Ff + col0;
    const float* Bu = w_up   + (size_t)e * Hd * Ff + col0;

    __shared__ __align__(16) float sA[2][128 * 16];
    __shared__ __align__(16) float sG[2][16 * 72];
    __shared__ __align__(16) float sU[2][16 * 72];

    int t = threadIdx.x, lane = t & 31, warp = t >> 5;
    int wm = warp >> 2, wn = warp & 3;
    int qr = lane >> 2, qc = lane & 3;

    // A fetch: c = t&3 (word-4 slot), rows r0, r0+64
    int c = t & 3, r0 = t >> 2;
    int pr = (r0 >> 1) & 3;              // same for r0 and r0+64
    const float* ap[2];
#pragma unroll
    for (int j = 0; j < 2; j++) {
        int r = row0 + r0 + 64 * j;
        ap[j] = (r < cnt) ? (x + (size_t)g_tok[e][r] * Hd + 4 * c) : nullptr;
    }
    // B fetch: n4 = t&15, kb = t>>4 (0..15), one vec per matrix
    int n4 = t & 15, kb = t >> 4;
    const float* bg = Bg + (size_t)kb * Ff + 4 * n4;
    const float* bu = Bu + (size_t)kb * Ff + 4 * n4;

    float accG[4][2][4], accU[4][2][4];
#pragma unroll
    for (int a = 0; a < 4; a++)
#pragma unroll
        for (int b = 0; b < 2; b++)
#pragma unroll
            for (int d = 0; d < 4; d++) { accG[a][b][d] = 0.f; accU[a][b][d] = 0.f; }

    float4 la[2], lg, lu;
    auto fetch = [&](int k0) {
#pragma unroll
        for (int j = 0; j < 2; j++)
            la[j] = ap[j] ? *(const float4*)(ap[j] + k0) : make_float4(0, 0, 0, 0);
        lg = *(const float4*)(bg + (size_t)k0 * Ff);
        lu = *(const float4*)(bu + (size_t)k0 * Ff);
    };
    auto stage = [&](int buf) {
#pragma unroll
        for (int j = 0; j < 2; j++) {
            float* rowp = &sA[buf][(r0 + 64 * j) * 16 + c];
            rowp[4 * (0 ^ pr)] = f2tf(la[j].x);
            rowp[4 * (1 ^ pr)] = f2tf(la[j].y);
            rowp[4 * (2 ^ pr)] = f2tf(la[j].z);
            rowp[4 * (3 ^ pr)] = f2tf(la[j].w);
        }
        float4 vg = make_float4(f2tf(lg.x), f2tf(lg.y), f2tf(lg.z), f2tf(lg.w));
        float4 vu = make_float4(f2tf(lu.x), f2tf(lu.y), f2tf(lu.z), f2tf(lu.w));
        *(float4*)&sG[buf][kb * 72 + 4 * n4] = vg;
        *(float4*)&sU[buf][kb * 72 + 4 * n4] = vu;
    };

    fetch(0); stage(0);
    __syncthreads();
    const int KT = Hd / 16;   // 64
    for (int kt = 0; kt < KT; kt++) {
        int buf = kt & 1;
        if (kt + 1 < KT) fetch((kt + 1) * 16);

        float4 alo[4], ahi[4];
#pragma unroll
        for (int mt = 0; mt < 4; mt++) {
            int R = wm * 64 + mt * 16 + qr;
            int s = 4 * (qc ^ ((R >> 1) & 3));
            alo[mt] = *(const float4*)&sA[buf][R * 16 + s];
            ahi[mt] = *(const float4*)&sA[buf][(R + 8) * 16 + s];
        }
#pragma unroll
        for (int nt = 0; nt < 2; nt++) {
            int n = wn * 16 + nt * 8 + qr;
#pragma unroll
            for (int ks = 0; ks < 2; ks++) {
                unsigned bgf[2] = { __float_as_uint(sG[buf][(ks * 8 + qc) * 72 + n]),
                                    __float_as_uint(sG[buf][(ks * 8 + qc + 4) * 72 + n]) };
                unsigned buf2[2] = { __float_as_uint(sU[buf][(ks * 8 + qc) * 72 + n]),
                                     __float_as_uint(sU[buf][(ks * 8 + qc + 4) * 72 + n]) };
#pragma unroll
                for (int mt = 0; mt < 4; mt++) {
                    const float* al = (const float*)&alo[mt];
                    const float* ah = (const float*)&ahi[mt];
                    unsigned af[4] = { __float_as_uint(al[2 * ks]), __float_as_uint(ah[2 * ks]),
                                       __float_as_uint(al[2 * ks + 1]), __float_as_uint(ah[2 * ks + 1]) };
                    mma8(accG[mt][nt], af, bgf);
                    mma8(accU[mt][nt], af, buf2);
                }
            }
        }
        if (kt + 1 < KT) stage(buf ^ 1);
        __syncthreads();
    }

    // epilogue: h = silu(g) * u -> g_h[tok*2+slot]
#pragma unroll
    for (int mt = 0; mt < 4; mt++) {
#pragma unroll
        for (int half = 0; half < 2; half++) {
            int r = row0 + wm * 64 + mt * 16 + qr + half * 8;
            if (r < cnt) {
                int aid = g_tok[e][r] * 2 + g_slot[e][r];
                float* hrow = g_h + (size_t)aid * Ff + col0;
#pragma unroll
                for (int nt = 0; nt < 2; nt++) {
                    float gg0 = accG[mt][nt][half * 2 + 0], gg1 = accG[mt][nt][half * 2 + 1];
                    float uu0 = accU[mt][nt][half * 2 + 0], uu1 = accU[mt][nt][half * 2 + 1];
                    float h0 = gg0 * uu0 / (1.f + __expf(-gg0));
                    float h1 = gg1 * uu1 / (1.f + __expf(-gg1));
                    int cc = wn * 16 + nt * 8 + 2 * qc;
                    *(float2*)(hrow + cc) = make_float2(h0, h1);
                }
            }
        }
    }
}

// ============================================================================
// GEMM2: block 128(M) x 128(N), 256 thr, warps 2x4 (tile 64x32)
// out_slot[tok] = w * (h[aid] @ Wd)
// ============================================================================
__global__ void __launch_bounds__(256) gemm2_kernel(const float* __restrict__ w_down)
{
    int e = blockIdx.z;
    int cnt = g_cnt[e];
    int row0 = blockIdx.y * 128;
    if (row0 >= cnt) return;
    int col0 = blockIdx.x * 128;
    const float* Bd = w_down + (size_t)e * Ff * Hd + col0;

    __shared__ __align__(16) float sA[2][128 * 16];
    __shared__ __align__(16) float sB[2][16 * 136];

    int t = threadIdx.x, lane = t & 31, warp = t >> 5;
    int wm = warp >> 2, wn = warp & 3;
    int qr = lane >> 2, qc = lane & 3;

    int c = t & 3, r0 = t >> 2;
    int pr = (r0 >> 1) & 3;
    const float* ap[2];
#pragma unroll
    for (int j = 0; j < 2; j++) {
        int r = row0 + r0 + 64 * j;
        if (r < cnt) {
            int aid = g_tok[e][r] * 2 + g_slot[e][r];
            ap[j] = g_h + (size_t)aid * Ff + 4 * c;
        } else ap[j] = nullptr;
    }
    // B fetch: n4 = lane (0..31), kb = warp (0..7), rows kb, kb+8
    int n4 = lane, kb = warp;
    const float* bp = Bd + 4 * n4;

    float acc[4][4][4];
#pragma unroll
    for (int a = 0; a < 4; a++)
#pragma unroll
        for (int b = 0; b < 4; b++)
#pragma unroll
            for (int d = 0; d < 4; d++) acc[a][b][d] = 0.f;

    float4 la[2], lb[2];
    auto fetch = [&](int k0) {
#pragma unroll
        for (int j = 0; j < 2; j++)
            la[j] = ap[j] ? *(const float4*)(ap[j] + k0) : make_float4(0, 0, 0, 0);
#pragma unroll
        for (int j = 0; j < 2; j++)
            lb[j] = *(const float4*)(bp + (size_t)(k0 + kb + 8 * j) * Hd);
    };
    auto stage = [&](int buf) {
#pragma unroll
        for (int j = 0; j < 2; j++) {
            float* rowp = &sA[buf][(r0 + 64 * j) * 16 + c];
            rowp[4 * (0 ^ pr)] = f2tf(la[j].x);
            rowp[4 * (1 ^ pr)] = f2tf(la[j].y);
            rowp[4 * (2 ^ pr)] = f2tf(la[j].z);
            rowp[4 * (3 ^ pr)] = f2tf(la[j].w);
        }
#pragma unroll
        for (int j = 0; j < 2; j++) {
            float4 v = make_float4(f2tf(lb[j].x), f2tf(lb[j].y), f2tf(lb[j].z), f2tf(lb[j].w));
            *(float4*)&sB[buf][(kb + 8 * j) * 136 + 4 * n4] = v;
        }
    };

    fetch(0); stage(0);
    __syncthreads();
    const int KT = Ff / 16;   // 256
    for (int kt = 0; kt < KT; kt++) {
        int buf = kt & 1;
        if (kt + 1 < KT) fetch((kt + 1) * 16);

        float4 alo[4], ahi[4];
#pragma unroll
        for (int mt = 0; mt < 4; mt++) {
            int R = wm * 64 + mt * 16 + qr;
            int s = 4 * (qc ^ ((R >> 1) & 3));
            alo[mt] = *(const float4*)&sA[buf][R * 16 + s];
            ahi[mt] = *(const float4*)&sA[buf][(R + 8) * 16 + s];
        }
#pragma unroll
        for (int nt = 0; nt < 4; nt++) {
            int n = wn * 32 + nt * 8 + qr;
#pragma unroll
            for (int ks = 0; ks < 2; ks++) {
                unsigned bf[2] = { __float_as_uint(sB[buf][(ks * 8 + qc) * 136 + n]),
                                   __float_as_uint(sB[buf][(ks * 8 + qc + 4) * 136 + n]) };
#pragma unroll
                for (int mt = 0; mt < 4; mt++) {
                    const float* al = (const float*)&alo[mt];
                    const float* ah = (const float*)&ahi[mt];
                    unsigned af[4] = { __float_as_uint(al[2 * ks]), __float_as_uint(ah[2 * ks]),
                                       __float_as_uint(al[2 * ks + 1]), __float_as_uint(ah[2 * ks + 1]) };
                    mma8(acc[mt][nt], af, bf);
                }
            }
        }
        if (kt + 1 < KT) stage(buf ^ 1);
        __syncthreads();
    }

#pragma unroll
    for (int mt = 0; mt < 4; mt++) {
#pragma unroll
        for (int half = 0; half < 2; half++) {
            int r = row0 + wm * 64 + mt * 16 + qr + half * 8;
            if (r < cnt) {
                int tok = g_tok[e][r];
                float w = g_wt[e][r];
                int sl  = g_slot[e][r];
                float* orow = g_sbuf + (size_t)sl * NT * Hd + (size_t)tok * Hd + col0;
#pragma unroll
                for (int nt = 0; nt < 4; nt++) {
                    int cc = wn * 32 + nt * 8 + 2 * qc;
                    *(float2*)(orow + cc) = make_float2(w * acc[mt][nt][half * 2 + 0],
                                                        w * acc[mt][nt][half * 2 + 1]);
                }
            }
        }
    }
}

__global__ void combine_kernel(float* __restrict__ out) {
    int i = blockIdx.x * 256 + threadIdx.x;
    if (i < NT * Hd / 4) {
        float4 a = ((const float4*)g_sbuf)[i];
        float4 b = ((const float4*)(g_sbuf + NT * Hd))[i];
        ((float4*)out)[i] = make_float4(a.x + b.x, a.y + b.y, a.z + b.z, a.w + b.w);
    }
}

// ---------------- launch ----------------
extern "C" void kernel_launch(void* const* d_in, const int* in_sizes, int n_in,
                              void* d_out, int out_size) {
    (void)in_sizes; (void)n_in; (void)out_size;
    const float* x      = (const float*)d_in[0];
    const float* gw     = (const float*)d_in[1];
    const float* w_gate = (const float*)d_in[2];
    const float* w_up   = (const float*)d_in[3];
    const float* w_down = (const float*)d_in[4];
    float* out = (float*)d_out;

    zero_kernel<<<1, 32>>>();
    router_kernel<<<NT / 8, 256>>>(x, gw);
    gemm1_kernel<<<dim3(Ff / 64, NT / 128, NE), 256>>>(x, w_gate, w_up);
    gemm2_kernel<<<dim3(Hd / 128, NT / 128, NE), 256>>>(w_down);
    combine_kernel<<<(NT * Hd / 4 + 255) / 256, 256>>>(out);
}

// round 9
// speedup vs baseline: 1.5061x; 1.5061x over previous
#include <cuda_runtime.h>
#include <cstdint>

// Problem constants
constexpr int Hd = 1024;   // hidden
constexpr int Ff = 4096;   // intermediate
constexpr int NE = 8;      // experts
constexpr int NT = 2048;   // tokens
constexpr int NA = 2 * NT; // assignments (top-2)

// ---------------- device scratch (no allocations allowed) ----------------
__device__ int   g_cnt[NE];
__device__ int   g_tok[NE][NT];
__device__ float g_wt[NE][NT];
__device__ int   g_slot[NE][NT];
__device__ float g_h[(size_t)NA * Ff];   // 64 MB fp32 intermediate, row = tok*2+slot
__device__ float g_sbuf[2 * NT * Hd];    // per-rank-slot output buffers

// ---------------- helpers ----------------
__device__ __forceinline__ float f2tf(float x) {
    unsigned u;
    asm("cvt.rna.tf32.f32 %0, %1;" : "=r"(u) : "f"(x));
    return __uint_as_float(u);
}
__device__ __forceinline__ void mma8(float c[4], const unsigned a[4], const unsigned b[2]) {
    asm volatile(
        "mma.sync.aligned.m16n8k8.row.col.f32.tf32.tf32.f32 "
        "{%0,%1,%2,%3},{%4,%5,%6,%7},{%8,%9},{%0,%1,%2,%3};"
        : "+f"(c[0]), "+f"(c[1]), "+f"(c[2]), "+f"(c[3])
        : "r"(a[0]), "r"(a[1]), "r"(a[2]), "r"(a[3]), "r"(b[0]), "r"(b[1]));
}

// ---------------- small kernels ----------------
__global__ void zero_kernel() {
    if (threadIdx.x < NE) g_cnt[threadIdx.x] = 0;
}

// One warp per token: logits -> softmax -> top-2 -> softmax of the two PROBS.
__global__ void router_kernel(const float* __restrict__ x, const float* __restrict__ gw) {
    int tok  = blockIdx.x * 8 + (threadIdx.x >> 5);
    int lane = threadIdx.x & 31;
    if (tok >= NT) return;
    const float* xr = x + (size_t)tok * Hd;

    float acc[NE];
#pragma unroll
    for (int e = 0; e < NE; e++) acc[e] = 0.f;
    for (int i = lane; i < Hd; i += 32) {
        float xv = xr[i];
        const float* g = gw + i * NE;
#pragma unroll
        for (int e = 0; e < NE; e++) acc[e] = fmaf(xv, g[e], acc[e]);
    }
#pragma unroll
    for (int e = 0; e < NE; e++) {
#pragma unroll
        for (int o = 16; o > 0; o >>= 1) acc[e] += __shfl_xor_sync(0xffffffffu, acc[e], o);
    }
    if (lane == 0) {
        float m = acc[0];
#pragma unroll
        for (int e = 1; e < NE; e++) m = fmaxf(m, acc[e]);
        float p[NE], s = 0.f;
#pragma unroll
        for (int e = 0; e < NE; e++) { p[e] = expf(acc[e] - m); s += p[e]; }
        float inv = 1.f / s;
#pragma unroll
        for (int e = 0; e < NE; e++) p[e] *= inv;

        int i0 = 0;
#pragma unroll
        for (int e = 1; e < NE; e++) if (p[e] > p[i0]) i0 = e;
        int i1 = (i0 == 0) ? 1 : 0;
#pragma unroll
        for (int e = 0; e < NE; e++) if (e != i0 && p[e] > p[i1]) i1 = e;

        float eb = expf(p[i1] - p[i0]);       // <= 1
        float w0 = 1.f / (1.f + eb);
        float w1 = 1.f - w0;

        int s0 = atomicAdd(&g_cnt[i0], 1);
        g_tok[i0][s0] = tok; g_wt[i0][s0] = w0; g_slot[i0][s0] = 0;
        int s1 = atomicAdd(&g_cnt[i1], 1);
        g_tok[i1][s1] = tok; g_wt[i1][s1] = w1; g_slot[i1][s1] = 1;
    }
}

// ============================================================================
// Layouts (unchanged from R8, both conflict-free):
//  A smem: [128 rows][16 words], k at word 4*((k%4) ^ ((row>>1)&3)) + k/4.
//  B smem: [16 k-rows][pitch], pitch 136 (N=128) / 72 (N=64).
// Execution (new): __launch_bounds__(256, 2) -> 2 CTAs/SM; B fragments for the
// whole k-tile loaded up front; M processed in halves (16 A-frag regs live).
// ============================================================================

// ============================================================================
// GEMM1: block 128(M) x 64(N), 256 thr, warps 2x4, fused gate+up.
// ============================================================================
__global__ void __launch_bounds__(256, 2) gemm1_kernel(
    const float* __restrict__ x,
    const float* __restrict__ w_gate,
    const float* __restrict__ w_up)
{
    int e = blockIdx.z;
    int cnt = g_cnt[e];
    int row0 = blockIdx.y * 128;
    if (row0 >= cnt) return;
    int col0 = blockIdx.x * 64;
    const float* Bg = w_gate + (size_t)e * Hd * Ff + col0;
    const float* Bu = w_up   + (size_t)e * Hd * Ff + col0;

    __shared__ __align__(16) float sA[2][128 * 16];
    __shared__ __align__(16) float sG[2][16 * 72];
    __shared__ __align__(16) float sU[2][16 * 72];

    int t = threadIdx.x, lane = t & 31, warp = t >> 5;
    int wm = warp >> 2, wn = warp & 3;
    int qr = lane >> 2, qc = lane & 3;

    int c = t & 3, r0 = t >> 2;
    int pr = (r0 >> 1) & 3;
    const float* ap[2];
#pragma unroll
    for (int j = 0; j < 2; j++) {
        int r = row0 + r0 + 64 * j;
        ap[j] = (r < cnt) ? (x + (size_t)g_tok[e][r] * Hd + 4 * c) : nullptr;
    }
    int n4 = t & 15, kb = t >> 4;
    const float* bg = Bg + (size_t)kb * Ff + 4 * n4;
    const float* bu = Bu + (size_t)kb * Ff + 4 * n4;

    float accG[4][2][4], accU[4][2][4];
#pragma unroll
    for (int a = 0; a < 4; a++)
#pragma unroll
        for (int b = 0; b < 2; b++)
#pragma unroll
            for (int d = 0; d < 4; d++) { accG[a][b][d] = 0.f; accU[a][b][d] = 0.f; }

    float4 la[2], lg, lu;
    auto fetch = [&](int k0) {
#pragma unroll
        for (int j = 0; j < 2; j++)
            la[j] = ap[j] ? *(const float4*)(ap[j] + k0) : make_float4(0, 0, 0, 0);
        lg = *(const float4*)(bg + (size_t)k0 * Ff);
        lu = *(const float4*)(bu + (size_t)k0 * Ff);
    };
    auto stage = [&](int buf) {
#pragma unroll
        for (int j = 0; j < 2; j++) {
            float* rowp = &sA[buf][(r0 + 64 * j) * 16 + c];
            rowp[4 * (0 ^ pr)] = f2tf(la[j].x);
            rowp[4 * (1 ^ pr)] = f2tf(la[j].y);
            rowp[4 * (2 ^ pr)] = f2tf(la[j].z);
            rowp[4 * (3 ^ pr)] = f2tf(la[j].w);
        }
        *(float4*)&sG[buf][kb * 72 + 4 * n4] =
            make_float4(f2tf(lg.x), f2tf(lg.y), f2tf(lg.z), f2tf(lg.w));
        *(float4*)&sU[buf][kb * 72 + 4 * n4] =
            make_float4(f2tf(lu.x), f2tf(lu.y), f2tf(lu.z), f2tf(lu.w));
    };

    fetch(0); stage(0);
    __syncthreads();
    const int KT = Hd / 16;   // 64
    for (int kt = 0; kt < KT; kt++) {
        int buf = kt & 1;
        if (kt + 1 < KT) fetch((kt + 1) * 16);

        // all B fragments for this k-tile
        unsigned bgf[2][2][2], buf2[2][2][2];
#pragma unroll
        for (int nt = 0; nt < 2; nt++) {
            int n = wn * 16 + nt * 8 + qr;
#pragma unroll
            for (int ks = 0; ks < 2; ks++) {
                bgf[nt][ks][0] = __float_as_uint(sG[buf][(ks * 8 + qc) * 72 + n]);
                bgf[nt][ks][1] = __float_as_uint(sG[buf][(ks * 8 + qc + 4) * 72 + n]);
                buf2[nt][ks][0] = __float_as_uint(sU[buf][(ks * 8 + qc) * 72 + n]);
                buf2[nt][ks][1] = __float_as_uint(sU[buf][(ks * 8 + qc + 4) * 72 + n]);
            }
        }
        // M in halves: 2 A fragments live at a time
#pragma unroll
        for (int mth = 0; mth < 2; mth++) {
            float4 alo[2], ahi[2];
#pragma unroll
            for (int m2 = 0; m2 < 2; m2++) {
                int R = wm * 64 + (mth * 2 + m2) * 16 + qr;
                int s = 4 * (qc ^ ((R >> 1) & 3));
                alo[m2] = *(const float4*)&sA[buf][R * 16 + s];
                ahi[m2] = *(const float4*)&sA[buf][(R + 8) * 16 + s];
            }
#pragma unroll
            for (int nt = 0; nt < 2; nt++)
#pragma unroll
                for (int ks = 0; ks < 2; ks++)
#pragma unroll
                    for (int m2 = 0; m2 < 2; m2++) {
                        const float* al = (const float*)&alo[m2];
                        const float* ah = (const float*)&ahi[m2];
                        unsigned af[4] = { __float_as_uint(al[2 * ks]), __float_as_uint(ah[2 * ks]),
                                           __float_as_uint(al[2 * ks + 1]), __float_as_uint(ah[2 * ks + 1]) };
                        mma8(accG[mth * 2 + m2][nt], af, bgf[nt][ks]);
                        mma8(accU[mth * 2 + m2][nt], af, buf2[nt][ks]);
                    }
        }
        if (kt + 1 < KT) stage(buf ^ 1);
        __syncthreads();
    }

    // epilogue: h = silu(g) * u -> g_h[tok*2+slot]
#pragma unroll
    for (int mt = 0; mt < 4; mt++) {
#pragma unroll
        for (int half = 0; half < 2; half++) {
            int r = row0 + wm * 64 + mt * 16 + qr + half * 8;
            if (r < cnt) {
                int aid = g_tok[e][r] * 2 + g_slot[e][r];
                float* hrow = g_h + (size_t)aid * Ff + col0;
#pragma unroll
                for (int nt = 0; nt < 2; nt++) {
                    float gg0 = accG[mt][nt][half * 2 + 0], gg1 = accG[mt][nt][half * 2 + 1];
                    float uu0 = accU[mt][nt][half * 2 + 0], uu1 = accU[mt][nt][half * 2 + 1];
                    float h0 = gg0 * uu0 / (1.f + __expf(-gg0));
                    float h1 = gg1 * uu1 / (1.f + __expf(-gg1));
                    int cc = wn * 16 + nt * 8 + 2 * qc;
                    *(float2*)(hrow + cc) = make_float2(h0, h1);
                }
            }
        }
    }
}

// ============================================================================
// GEMM2: block 128(M) x 128(N), 256 thr, warps 2x4 (tile 64x32)
// ============================================================================
__global__ void __launch_bounds__(256, 2) gemm2_kernel(const float* __restrict__ w_down)
{
    int e = blockIdx.z;
    int cnt = g_cnt[e];
    int row0 = blockIdx.y * 128;
    if (row0 >= cnt) return;
    int col0 = blockIdx.x * 128;
    const float* Bd = w_down + (size_t)e * Ff * Hd + col0;

    __shared__ __align__(16) float sA[2][128 * 16];
    __shared__ __align__(16) float sB[2][16 * 136];

    int t = threadIdx.x, lane = t & 31, warp = t >> 5;
    int wm = warp >> 2, wn = warp & 3;
    int qr = lane >> 2, qc = lane & 3;

    int c = t & 3, r0 = t >> 2;
    int pr = (r0 >> 1) & 3;
    const float* ap[2];
#pragma unroll
    for (int j = 0; j < 2; j++) {
        int r = row0 + r0 + 64 * j;
        if (r < cnt) {
            int aid = g_tok[e][r] * 2 + g_slot[e][r];
            ap[j] = g_h + (size_t)aid * Ff + 4 * c;
        } else ap[j] = nullptr;
    }
    int n4 = lane, kb = warp;
    const float* bp = Bd + 4 * n4;

    float acc[4][4][4];
#pragma unroll
    for (int a = 0; a < 4; a++)
#pragma unroll
        for (int b = 0; b < 4; b++)
#pragma unroll
            for (int d = 0; d < 4; d++) acc[a][b][d] = 0.f;

    float4 la[2], lb[2];
    auto fetch = [&](int k0) {
#pragma unroll
        for (int j = 0; j < 2; j++)
            la[j] = ap[j] ? *(const float4*)(ap[j] + k0) : make_float4(0, 0, 0, 0);
#pragma unroll
        for (int j = 0; j < 2; j++)
            lb[j] = *(const float4*)(bp + (size_t)(k0 + kb + 8 * j) * Hd);
    };
    auto stage = [&](int buf) {
#pragma unroll
        for (int j = 0; j < 2; j++) {
            float* rowp = &sA[buf][(r0 + 64 * j) * 16 + c];
            rowp[4 * (0 ^ pr)] = f2tf(la[j].x);
            rowp[4 * (1 ^ pr)] = f2tf(la[j].y);
            rowp[4 * (2 ^ pr)] = f2tf(la[j].z);
            rowp[4 * (3 ^ pr)] = f2tf(la[j].w);
        }
#pragma unroll
        for (int j = 0; j < 2; j++)
            *(float4*)&sB[buf][(kb + 8 * j) * 136 + 4 * n4] =
                make_float4(f2tf(lb[j].x), f2tf(lb[j].y), f2tf(lb[j].z), f2tf(lb[j].w));
    };

    fetch(0); stage(0);
    __syncthreads();
    const int KT = Ff / 16;   // 256
    for (int kt = 0; kt < KT; kt++) {
        int buf = kt & 1;
        if (kt + 1 < KT) fetch((kt + 1) * 16);

        unsigned bf[4][2][2];
#pragma unroll
        for (int nt = 0; nt < 4; nt++) {
            int n = wn * 32 + nt * 8 + qr;
#pragma unroll
            for (int ks = 0; ks < 2; ks++) {
                bf[nt][ks][0] = __float_as_uint(sB[buf][(ks * 8 + qc) * 136 + n]);
                bf[nt][ks][1] = __float_as_uint(sB[buf][(ks * 8 + qc + 4) * 136 + n]);
            }
        }
#pragma unroll
        for (int mth = 0; mth < 2; mth++) {
            float4 alo[2], ahi[2];
#pragma unroll
            for (int m2 = 0; m2 < 2; m2++) {
                int R = wm * 64 + (mth * 2 + m2) * 16 + qr;
                int s = 4 * (qc ^ ((R >> 1) & 3));
                alo[m2] = *(const float4*)&sA[buf][R * 16 + s];
                ahi[m2] = *(const float4*)&sA[buf][(R + 8) * 16 + s];
            }
#pragma unroll
            for (int nt = 0; nt < 4; nt++)
#pragma unroll
                for (int ks = 0; ks < 2; ks++)
#pragma unroll
                    for (int m2 = 0; m2 < 2; m2++) {
                        const float* al = (const float*)&alo[m2];
                        const float* ah = (const float*)&ahi[m2];
                        unsigned af[4] = { __float_as_uint(al[2 * ks]), __float_as_uint(ah[2 * ks]),
                                           __float_as_uint(al[2 * ks + 1]), __float_as_uint(ah[2 * ks + 1]) };
                        mma8(acc[mth * 2 + m2][nt], af, bf[nt][ks]);
                    }
        }
        if (kt + 1 < KT) stage(buf ^ 1);
        __syncthreads();
    }

#pragma unroll
    for (int mt = 0; mt < 4; mt++) {
#pragma unroll
        for (int half = 0; half < 2; half++) {
            int r = row0 + wm * 64 + mt * 16 + qr + half * 8;
            if (r < cnt) {
                int tok = g_tok[e][r];
                float w = g_wt[e][r];
                int sl  = g_slot[e][r];
                float* orow = g_sbuf + (size_t)sl * NT * Hd + (size_t)tok * Hd + col0;
#pragma unroll
                for (int nt = 0; nt < 4; nt++) {
                    int cc = wn * 32 + nt * 8 + 2 * qc;
                    *(float2*)(orow + cc) = make_float2(w * acc[mt][nt][half * 2 + 0],
                                                        w * acc[mt][nt][half * 2 + 1]);
                }
            }
        }
    }
}

__global__ void combine_kernel(float* __restrict__ out) {
    int i = blockIdx.x * 256 + threadIdx.x;
    if (i < NT * Hd / 4) {
        float4 a = ((const float4*)g_sbuf)[i];
        float4 b = ((const float4*)(g_sbuf + NT * Hd))[i];
        ((float4*)out)[i] = make_float4(a.x + b.x, a.y + b.y, a.z + b.z, a.w + b.w);
    }
}

// ---------------- launch ----------------
extern "C" void kernel_launch(void* const* d_in, const int* in_sizes, int n_in,
                              void* d_out, int out_size) {
    (void)in_sizes; (void)n_in; (void)out_size;
    const float* x      = (const float*)d_in[0];
    const float* gw     = (const float*)d_in[1];
    const float* w_gate = (const float*)d_in[2];
    const float* w_up   = (const float*)d_in[3];
    const float* w_down = (const float*)d_in[4];
    float* out = (float*)d_out;

    zero_kernel<<<1, 32>>>();
    router_kernel<<<NT / 8, 256>>>(x, gw);
    gemm1_kernel<<<dim3(Ff / 64, NT / 128, NE), 256>>>(x, w_gate, w_up);
    gemm2_kernel<<<dim3(Hd / 128, NT / 128, NE), 256>>>(w_down);
    combine_kernel<<<(NT * Hd / 4 + 255) / 256, 256>>>(out);
}